// round 16
// baseline (speedup 1.0000x reference)
#include <cuda_runtime.h>
#include <cuda_fp16.h>
#include <cstdint>

#define NCLS   13
#define PD     128
#define BM     64
#define NTHR   256
#define MINPTS 256.0f

// packed fp16 weight offsets (K padded to mult of 16), element counts in halfs
#define OFF1 0                    // 16*256   = 4096
#define OFF2 4096                 // 256*512  = 131072
#define OFF3 (OFF2 + 131072)      // 512*256  = 131072
#define OFF4 (OFF3 + 131072)      // 256*128  = 32768
#define WPTOT (OFF4 + 32768)

__device__ __align__(16) __half g_wp[WPTOT];
__device__ float  g_sums[NCLS * PD];
__device__ int    g_counts[NCLS];

// ---- fp16 mma m16n8k16, f16 accumulate (2x rate, 2 regs per tile) ----
__device__ __forceinline__ void mma_h16(uint32_t* c, uint32_t a0, uint32_t a1,
                                        uint32_t a2, uint32_t a3,
                                        uint32_t b0, uint32_t b1) {
    asm volatile(
        "mma.sync.aligned.m16n8k16.row.col.f16.f16.f16.f16 "
        "{%0,%1}, {%2,%3,%4,%5}, {%6,%7}, {%0,%1};\n"
        : "+r"(c[0]), "+r"(c[1])
        : "r"(a0), "r"(a1), "r"(a2), "r"(a3), "r"(b0), "r"(b1));
}
// ---- ldmatrix x4: one instruction loads a full m16k16 A fragment ----
__device__ __forceinline__ void ldmx4(uint32_t& r0, uint32_t& r1,
                                      uint32_t& r2, uint32_t& r3, uint32_t addr) {
    asm volatile("ldmatrix.sync.aligned.m8n8.x4.shared.b16 {%0,%1,%2,%3}, [%4];"
                 : "=r"(r0), "=r"(r1), "=r"(r2), "=r"(r3) : "r"(addr));
}

// ---------------- kernel 0: zero scratch ----------------
__global__ void zero_kernel() {
    int i = blockIdx.x * blockDim.x + threadIdx.x;
    if (i < NCLS * PD) g_sums[i] = 0.f;
    if (i < NCLS) g_counts[i] = 0;
}

// ---------------- kernel 1: per-class counts ----------------
__global__ void count_kernel(const int* __restrict__ y, int P) {
    __shared__ int sc[NCLS];
    if (threadIdx.x < NCLS) sc[threadIdx.x] = 0;
    __syncthreads();
    for (int i = blockIdx.x * blockDim.x + threadIdx.x; i < P;
         i += gridDim.x * blockDim.x)
        atomicAdd(&sc[y[i]], 1);
    __syncthreads();
    if (threadIdx.x < NCLS) atomicAdd(&g_counts[threadIdx.x], sc[threadIdx.x]);
}

// ---------------- kernel 2: pack ALL weights (pair-packed for LDG.128) ----------------
// 8 halfs per (jp,kc,lane): [j=2jp frag (4h)][j=2jp+1 frag (4h)]
// frag halfs: [k0,k0+1,k0+8,k0+9], k0 = kc*16 + 2r, n = j*8 + q  (r=lane&3, q=lane>>2)
__device__ __forceinline__ void pack_one(const float* __restrict__ src,
                                         __half* __restrict__ dst,
                                         int p, int K, int N, int Ksrc) {
    int t = p & 3;
    int h = (p >> 2) & 1;
    int lane = (p >> 3) & 31;
    int rest = p >> 8;
    int kc = rest % (K >> 4);
    int jp = rest / (K >> 4);
    int r = lane & 3, q = lane >> 2;
    int j = jp * 2 + h;
    int k = kc * 16 + 2 * r + (t & 1) + 8 * (t >> 1);
    int n = j * 8 + q;
    float v = (k < Ksrc) ? src[k * N + n] : 0.f;
    dst[p] = __float2half(v);
}
__global__ void pack_all_kernel(const float* __restrict__ We1, const float* __restrict__ We2,
                                const float* __restrict__ W1, const float* __restrict__ W2) {
    int p = blockIdx.x * blockDim.x + threadIdx.x;
    if (p < 4096)                    pack_one(We1, g_wp + OFF1, p, 16, 256, 7);
    else if (p < 4096 + 131072)      pack_one(We2, g_wp + OFF2, p - 4096, 256, 512, 256);
    else if (p < 4096 + 262144)      pack_one(W1,  g_wp + OFF3, p - 135168, 512, 256, 512);
    else if (p < WPTOT)              pack_one(W2,  g_wp + OFF4, p - 266240, 256, 128, 256);
}

// ---------------- fp16 mma layer (ldmatrix A, f16 single-chain acc) ----------------
// A in shared: PLAIN row-major halfs [BM][ASTR].
// ASTR bytes ≡ odd*16 (mod 128) -> ldmatrix conflict-free (8 rows tile the line).
// W pair-packed: one uint4 per (jp,kc,lane) = fragments for j=2jp, 2jp+1.
// LASTL: also accumulates per-row sum-of-squares into sSq via quad-shfl + atomic.
template <int K, int N, int ASTR, int CSTR, int MT, int NT, bool LASTL>
__device__ __forceinline__ void mma_layer(
    const __half* __restrict__ Wp, const float* __restrict__ bias,
    const __half* __restrict__ Ash, void* __restrict__ Cout,
    float* __restrict__ sSq,
    int warp, int lane)
{
    const int r = lane & 3, q = lane >> 2;
    constexpr int SLICE = N / 8;
    constexpr int NCH = SLICE / (NT * 8);
    constexpr int KC = K / 16;
    // ldmatrix per-lane source address (tile-ordered: m0-7/kLo, m8-15/kLo, m0-7/kHi, m8-15/kHi)
    const int tile = lane >> 3, rr = lane & 7;
    const uint32_t aBase = (uint32_t)__cvta_generic_to_shared(Ash)
        + (uint32_t)((((tile & 1) * 8 + rr) * ASTR + (tile >> 1) * 8) * 2);
    #pragma unroll
    for (int ch = 0; ch < NCH; ch++) {
        const int nbase = warp * SLICE + ch * NT * 8;
        const int jp0 = nbase >> 4;
        uint32_t hacc[MT][NT][2];
        #pragma unroll
        for (int mt = 0; mt < MT; mt++)
            #pragma unroll
            for (int nt = 0; nt < NT; nt++) {
                hacc[mt][nt][0] = 0u;
                hacc[mt][nt][1] = 0u;
            }

        #pragma unroll 8
        for (int kc = 0; kc < KC; kc++) {
            uint32_t a[MT][4];
            #pragma unroll
            for (int mt = 0; mt < MT; mt++)
                ldmx4(a[mt][0], a[mt][1], a[mt][2], a[mt][3],
                      aBase + (uint32_t)(mt * 16 * ASTR * 2 + kc * 32));
            uint4 bp[NT / 2];
            #pragma unroll
            for (int n2 = 0; n2 < NT / 2; n2++)
                bp[n2] = *(const uint4*)&Wp[(size_t)(((jp0 + n2) * KC + kc) * 32 + lane) * 8];
            #pragma unroll
            for (int mt = 0; mt < MT; mt++)
                #pragma unroll
                for (int n2 = 0; n2 < NT / 2; n2++) {
                    mma_h16(hacc[mt][2*n2],   a[mt][0], a[mt][1],
                            a[mt][2], a[mt][3], bp[n2].x, bp[n2].y);
                    mma_h16(hacc[mt][2*n2+1], a[mt][0], a[mt][1],
                            a[mt][2], a[mt][3], bp[n2].z, bp[n2].w);
                }
        }
        // epilogue: bias + relu (f32 math), PLAIN column layout
        float rowsq[LASTL ? MT : 1][LASTL ? 2 : 1];
        if (LASTL) {
            #pragma unroll
            for (int mt = 0; mt < MT; mt++) { rowsq[mt][0] = 0.f; rowsq[mt][1] = 0.f; }
        }
        #pragma unroll
        for (int nt = 0; nt < NT; nt++) {
            int c0 = nbase + nt * 8 + 2 * r;
            float b0 = bias[c0], b1 = bias[c0 + 1];
            #pragma unroll
            for (int mt = 0; mt < MT; mt++) {
                int m0 = mt * 16 + q, m1 = m0 + 8;
                float2 f0 = __half22float2(*(__half2*)&hacc[mt][nt][0]);
                float2 f1 = __half22float2(*(__half2*)&hacc[mt][nt][1]);
                float v00 = fmaxf(f0.x + b0, 0.f);
                float v01 = fmaxf(f0.y + b1, 0.f);
                float v10 = fmaxf(f1.x + b0, 0.f);
                float v11 = fmaxf(f1.y + b1, 0.f);
                if (LASTL) {
                    float* C = (float*)Cout;
                    *(float2*)&C[m0 * CSTR + c0] = make_float2(v00, v01);
                    *(float2*)&C[m1 * CSTR + c0] = make_float2(v10, v11);
                    rowsq[mt][0] += v00 * v00 + v01 * v01;
                    rowsq[mt][1] += v10 * v10 + v11 * v11;
                } else {
                    __half* C = (__half*)Cout;
                    *(__half2*)&C[m0 * CSTR + c0] = __floats2half2_rn(v00, v01);
                    *(__half2*)&C[m1 * CSTR + c0] = __floats2half2_rn(v10, v11);
                }
            }
        }
        if (LASTL) {
            #pragma unroll
            for (int mt = 0; mt < MT; mt++) {
                float s0 = rowsq[mt][0], s1 = rowsq[mt][1];
                s0 += __shfl_xor_sync(0xffffffffu, s0, 1);
                s0 += __shfl_xor_sync(0xffffffffu, s0, 2);
                s1 += __shfl_xor_sync(0xffffffffu, s1, 1);
                s1 += __shfl_xor_sync(0xffffffffu, s1, 2);
                if (r == 0) {
                    atomicAdd(&sSq[mt * 16 + q], s0);
                    atomicAdd(&sSq[mt * 16 + q + 8], s1);
                }
            }
        }
    }
}

// ---------------- kernel 3 (ncu launch index 3): fused MLP ----------------
// smem bytes: bufB_h 64*520*2=66560 (overlay bufF f32 64*132*4=33792)
//             bufA_h 64*264*2=33792 (overlay sSum 2*13*128*4=13312 after L4)
//             bufI_h 64*24*2=3072,  extras 1024   -> 104448 total (2 CTAs/SM)
#define SMEM_BYTES (66560 + 33792 + 3072 + 1024)

__global__ __launch_bounds__(NTHR, 2)
void mlp_kernel(const float* __restrict__ pos, const float* __restrict__ x,
                const int* __restrict__ y,
                const float* __restrict__ be1, const float* __restrict__ be2,
                const float* __restrict__ b1,  const float* __restrict__ b2,
                float* __restrict__ out, int P, int Npts)
{
    extern __shared__ __align__(16) char smraw[];
    __half* bufB = (__half*)smraw;                      // [64][520]
    __half* bufA = (__half*)(smraw + 66560);            // [64][264]
    __half* bufI = (__half*)(smraw + 66560 + 33792);    // [64][24]
    float*  sInv = (float*)(smraw + 66560 + 33792 + 3072);   // 64
    float*  sLbl = sInv + 64;                           // 64
    int*    sLab = (int*)(sLbl + 64);                   // 64
    float*  sSq  = (float*)(sLab + 64);                 // 64
    float*  bufF = (float*)smraw;                       // overlay [64][132]
    float*  sSum = (float*)(smraw + 66560);             // overlay 2*13*128

    const int tid  = threadIdx.x;
    const int lane = tid & 31, warp = tid >> 5;
    const int base = blockIdx.x * BM;
    const bool full = (base + BM <= P);    // P % BM == 0 on this dataset -> all blocks full

    // ---- load inputs into bufI [64][24] (plain layout, cols 0..15 valid) ----
    if (full) {
        for (int i = tid; i < BM * 16; i += NTHR) {
            int m = i >> 4, c = i & 15;
            int p = base + m;
            float v = 0.f;
            if (c < 7) {
                int b = p / Npts, n = p - b * Npts;
                if (c < 4) v = x[((size_t)b * 4 + c) * Npts + n];
                else       v = pos[(size_t)p * 3 + (c - 4)];
            }
            bufI[m * 24 + c] = __float2half(v);
        }
    } else {
        for (int i = tid; i < BM * 16; i += NTHR) {
            int m = i >> 4, c = i & 15;
            int p = base + m;
            float v = 0.f;
            if (p < P && c < 7) {
                int b = p / Npts, n = p - b * Npts;
                if (c < 4) v = x[((size_t)b * 4 + c) * Npts + n];
                else       v = pos[(size_t)p * 3 + (c - 4)];
            }
            bufI[m * 24 + c] = __float2half(v);
        }
    }
    if (tid < BM) {
        int p = base + tid;
        int l = (p < P) ? y[p] : 0;
        sLab[tid] = l;
        float cnt = (float)g_counts[l];
        sLbl[tid] = (cnt >= MINPTS) ? (float)l : -1.f;
        sSq[tid]  = 0.f;
    }
    __syncthreads();

    // ---- MLP chain (f16-acc single chain; ldmatrix A loads) ----
    mma_layer<16,  256, 24,  264, 4, 4, false>(g_wp + OFF1, be1, bufI, bufA, sSq, warp, lane);
    __syncthreads();
    mma_layer<256, 512, 264, 520, 4, 4, false>(g_wp + OFF2, be2, bufA, bufB, sSq, warp, lane);
    __syncthreads();
    mma_layer<512, 256, 520, 264, 4, 4, false>(g_wp + OFF3, b1,  bufB, bufA, sSq, warp, lane);
    __syncthreads();
    mma_layer<256, 128, 264, 132, 4, 2, true >(g_wp + OFF4, b2,  bufA, bufF, sSq, warp, lane);
    __syncthreads();

    // ---- zero sum overlay (bufA dead now) + row inverse norms from fused ssq ----
    for (int i = tid; i < 2 * NCLS * PD; i += NTHR) sSum[i] = 0.f;
    if (tid < BM)
        sInv[tid] = 1.f / fmaxf(sqrtf(sSq[tid]), 1e-12f);
    __syncthreads();

    // ---- per-class sums (2 race-free shared copies) ----
    {
        int n = tid & 127, half = tid >> 7;
        float* dst = sSum + half * NCLS * PD + n;
        if (full) {
            #pragma unroll 4
            for (int mm = 0; mm < 32; mm++) {
                int m = (half << 5) + mm;
                dst[sLab[m] * PD] += bufF[m * 132 + n] * sInv[m];
            }
        } else {
            for (int mm = 0; mm < 32; mm++) {
                int m = (half << 5) + mm;
                if (base + m < P)
                    dst[sLab[m] * PD] += bufF[m * 132 + n] * sInv[m];
            }
        }
    }
    __syncthreads();
    for (int i = tid; i < NCLS * PD; i += NTHR)
        atomicAdd(&g_sums[i], sSum[i] + sSum[NCLS * PD + i]);

    // ---- write current_prior rows [64][129] (incremental addressing) ----
    {
        size_t gbase = (size_t)base * 129;
        int c = tid & 127, mrow = tid >> 7;              // 2 rows x 128 cols per pass
        const float* src = bufF + mrow * 132 + c;
        float* dst = out + gbase + (size_t)mrow * 129 + c;
        if (full) {
            #pragma unroll 4
            for (int mm = mrow; mm < BM; mm += 2) {
                *dst = (*src) * sInv[mm];
                src += 2 * 132;
                dst += 2 * 129;
            }
            for (int mm = tid; mm < BM; mm += NTHR)
                out[gbase + (size_t)mm * 129 + 128] = sLbl[mm];
        } else {
            for (int mm = mrow; mm < BM; mm += 2) {
                if (base + mm < P) *dst = (*src) * sInv[mm];
                src += 2 * 132;
                dst += 2 * 129;
            }
            for (int mm = tid; mm < BM; mm += NTHR)
                if (base + mm < P) out[gbase + (size_t)mm * 129 + 128] = sLbl[mm];
        }
    }
}

// ---------------- kernel 4: EMA prior update (one warp per class) ----------------
__global__ void prior_kernel(const float* __restrict__ prior, float* __restrict__ out, int P) {
    int w = threadIdx.x >> 5;
    int lane = threadIdx.x & 31;
    if (w >= NCLS) return;
    float cnt = (float)g_counts[w];
    bool valid = (cnt >= MINPTS);
    float inv_cnt = 1.f / fmaxf(cnt, 1.f);
    float4 s4 = *(const float4*)&g_sums[w * PD + lane * 4];
    float4 p4 = *(const float4*)&prior[w * PD + lane * 4];
    float v[4];
    float pe[4] = {p4.x, p4.y, p4.z, p4.w};
    float mn[4] = {s4.x * inv_cnt, s4.y * inv_cnt, s4.z * inv_cnt, s4.w * inv_cnt};
    float ss = 0.f;
    #pragma unroll
    for (int i = 0; i < 4; i++) {
        float cur = valid ? mn[i] : pe[i];
        v[i] = 0.999f * pe[i] + 0.001f * cur;
        ss += v[i] * v[i];
    }
    #pragma unroll
    for (int o = 16; o > 0; o >>= 1) ss += __shfl_xor_sync(0xffffffffu, ss, o);
    float inv = 1.f / fmaxf(sqrtf(ss), 1e-12f);
    *(float4*)&out[(size_t)P * 129 + w * PD + lane * 4] =
        make_float4(v[0] * inv, v[1] * inv, v[2] * inv, v[3] * inv);
}

// ---------------- launch (mlp_kernel is launch index 3) ----------------
extern "C" void kernel_launch(void* const* d_in, const int* in_sizes, int n_in,
                              void* d_out, int out_size)
{
    const float* pos = (const float*)d_in[0];
    const float* x   = (const float*)d_in[1];
    const int*   y   = (const int*)  d_in[2];
    const float* We1 = (const float*)d_in[3];
    const float* be1 = (const float*)d_in[4];
    const float* We2 = (const float*)d_in[5];
    const float* be2 = (const float*)d_in[6];
    const float* W1  = (const float*)d_in[7];
    const float* b1  = (const float*)d_in[8];
    const float* W2  = (const float*)d_in[9];
    const float* b2  = (const float*)d_in[10];
    const float* pe  = (const float*)d_in[11];
    float* out = (float*)d_out;

    int P    = in_sizes[2];
    int B    = in_sizes[0] / 3 / 40000;
    int Npts = (B > 0) ? (in_sizes[0] / 3 / B) : 40000;

    cudaFuncSetAttribute(mlp_kernel, cudaFuncAttributeMaxDynamicSharedMemorySize, SMEM_BYTES);

    zero_kernel<<<7, 256>>>();                               // 0
    count_kernel<<<(P + 255) / 256, 256>>>(y, P);            // 1
    pack_all_kernel<<<(WPTOT + 255) / 256, 256>>>(We1, We2, W1, W2); // 2
    mlp_kernel<<<(P + BM - 1) / BM, NTHR, SMEM_BYTES>>>(pos, x, y, be1, be2,
                                                        b1, b2, out, P, Npts); // 3
    prior_kernel<<<1, 416>>>(pe, out, P);                    // 4
}

// round 17
// speedup vs baseline: 1.0241x; 1.0241x over previous
#include <cuda_runtime.h>
#include <cuda_fp16.h>
#include <cstdint>

#define NCLS   13
#define PD     128
#define BM     64
#define NTHR   256
#define MINPTS 256.0f

// packed fp16 weight offsets (K padded to mult of 16), element counts in halfs
#define OFF1 0                    // 16*256   = 4096
#define OFF2 4096                 // 256*512  = 131072
#define OFF3 (OFF2 + 131072)      // 512*256  = 131072
#define OFF4 (OFF3 + 131072)      // 256*128  = 32768
#define WPTOT (OFF4 + 32768)

__device__ __align__(16) __half g_wp[WPTOT];
__device__ float  g_sums[NCLS * PD];
__device__ int    g_counts[NCLS];

// ---- fp16 mma m16n8k16, f16 accumulate (2x rate, 2 regs per tile) ----
__device__ __forceinline__ void mma_h16(uint32_t* c, uint32_t a0, uint32_t a1,
                                        uint32_t a2, uint32_t a3,
                                        uint32_t b0, uint32_t b1) {
    asm volatile(
        "mma.sync.aligned.m16n8k16.row.col.f16.f16.f16.f16 "
        "{%0,%1}, {%2,%3,%4,%5}, {%6,%7}, {%0,%1};\n"
        : "+r"(c[0]), "+r"(c[1])
        : "r"(a0), "r"(a1), "r"(a2), "r"(a3), "r"(b0), "r"(b1));
}
// ---- ldmatrix x4: one instruction loads a full m16k16 A fragment ----
__device__ __forceinline__ void ldmx4(uint32_t& r0, uint32_t& r1,
                                      uint32_t& r2, uint32_t& r3, uint32_t addr) {
    asm volatile("ldmatrix.sync.aligned.m8n8.x4.shared.b16 {%0,%1,%2,%3}, [%4];"
                 : "=r"(r0), "=r"(r1), "=r"(r2), "=r"(r3) : "r"(addr));
}

// ---------------- kernel 0: zero scratch ----------------
__global__ void zero_kernel() {
    for (int i = threadIdx.x; i < NCLS * PD; i += blockDim.x) g_sums[i] = 0.f;
    if (threadIdx.x < NCLS) g_counts[threadIdx.x] = 0;
}

// ---------------- kernel 1: per-class counts ----------------
__global__ void count_kernel(const int* __restrict__ y, int P) {
    __shared__ int sc[NCLS];
    if (threadIdx.x < NCLS) sc[threadIdx.x] = 0;
    __syncthreads();
    for (int i = blockIdx.x * blockDim.x + threadIdx.x; i < P;
         i += gridDim.x * blockDim.x)
        atomicAdd(&sc[y[i]], 1);
    __syncthreads();
    if (threadIdx.x < NCLS) atomicAdd(&g_counts[threadIdx.x], sc[threadIdx.x]);
}

// ---------------- kernel 2: pack ALL weights (pair-packed for LDG.128) ----------------
// 8 halfs per (jp,kc,lane): [j=2jp frag (4h)][j=2jp+1 frag (4h)]
// frag halfs: [k0,k0+1,k0+8,k0+9], k0 = kc*16 + 2r, n = j*8 + q  (r=lane&3, q=lane>>2)
__device__ __forceinline__ void pack_one(const float* __restrict__ src,
                                         __half* __restrict__ dst,
                                         int p, int K, int N, int Ksrc) {
    int t = p & 3;
    int h = (p >> 2) & 1;
    int lane = (p >> 3) & 31;
    int rest = p >> 8;
    int kc = rest % (K >> 4);
    int jp = rest / (K >> 4);
    int r = lane & 3, q = lane >> 2;
    int j = jp * 2 + h;
    int k = kc * 16 + 2 * r + (t & 1) + 8 * (t >> 1);
    int n = j * 8 + q;
    float v = (k < Ksrc) ? src[k * N + n] : 0.f;
    dst[p] = __float2half(v);
}
__global__ void pack_all_kernel(const float* __restrict__ We1, const float* __restrict__ We2,
                                const float* __restrict__ W1, const float* __restrict__ W2) {
    int p = blockIdx.x * blockDim.x + threadIdx.x;
    if (p < 4096)                    pack_one(We1, g_wp + OFF1, p, 16, 256, 7);
    else if (p < 4096 + 131072)      pack_one(We2, g_wp + OFF2, p - 4096, 256, 512, 256);
    else if (p < 4096 + 262144)      pack_one(W1,  g_wp + OFF3, p - 135168, 512, 256, 512);
    else if (p < WPTOT)              pack_one(W2,  g_wp + OFF4, p - 266240, 256, 128, 256);
}

// ---------------- fp16 mma layer (ldmatrix A, f16 single-chain acc) ----------------
// A in shared: PLAIN row-major halfs [BM][ASTR].
// ASTR bytes ≡ odd*16 (mod 128) -> ldmatrix conflict-free (8 rows tile the line).
// W pair-packed: one uint4 per (jp,kc,lane) = fragments for j=2jp, 2jp+1.
// LASTL: also accumulates per-row sum-of-squares into sSq via quad-shfl + atomic.
template <int K, int N, int ASTR, int CSTR, int MT, int NT, bool LASTL>
__device__ __forceinline__ void mma_layer(
    const __half* __restrict__ Wp, const float* __restrict__ bias,
    const __half* __restrict__ Ash, void* __restrict__ Cout,
    float* __restrict__ sSq,
    int warp, int lane)
{
    const int r = lane & 3, q = lane >> 2;
    constexpr int SLICE = N / 8;
    constexpr int NCH = SLICE / (NT * 8);
    constexpr int KC = K / 16;
    // ldmatrix per-lane source address (tile-ordered: m0-7/kLo, m8-15/kLo, m0-7/kHi, m8-15/kHi)
    const int tile = lane >> 3, rr = lane & 7;
    const uint32_t aBase = (uint32_t)__cvta_generic_to_shared(Ash)
        + (uint32_t)((((tile & 1) * 8 + rr) * ASTR + (tile >> 1) * 8) * 2);
    #pragma unroll
    for (int ch = 0; ch < NCH; ch++) {
        const int nbase = warp * SLICE + ch * NT * 8;
        const int jp0 = nbase >> 4;
        uint32_t hacc[MT][NT][2];
        #pragma unroll
        for (int mt = 0; mt < MT; mt++)
            #pragma unroll
            for (int nt = 0; nt < NT; nt++) {
                hacc[mt][nt][0] = 0u;
                hacc[mt][nt][1] = 0u;
            }

        #pragma unroll 8
        for (int kc = 0; kc < KC; kc++) {
            uint32_t a[MT][4];
            #pragma unroll
            for (int mt = 0; mt < MT; mt++)
                ldmx4(a[mt][0], a[mt][1], a[mt][2], a[mt][3],
                      aBase + (uint32_t)(mt * 16 * ASTR * 2 + kc * 32));
            uint4 bp[NT / 2];
            #pragma unroll
            for (int n2 = 0; n2 < NT / 2; n2++)
                bp[n2] = *(const uint4*)&Wp[(size_t)(((jp0 + n2) * KC + kc) * 32 + lane) * 8];
            #pragma unroll
            for (int mt = 0; mt < MT; mt++)
                #pragma unroll
                for (int n2 = 0; n2 < NT / 2; n2++) {
                    mma_h16(hacc[mt][2*n2],   a[mt][0], a[mt][1],
                            a[mt][2], a[mt][3], bp[n2].x, bp[n2].y);
                    mma_h16(hacc[mt][2*n2+1], a[mt][0], a[mt][1],
                            a[mt][2], a[mt][3], bp[n2].z, bp[n2].w);
                }
        }
        // epilogue: bias + relu (f32 math), PLAIN column layout
        float rowsq[LASTL ? MT : 1][LASTL ? 2 : 1];
        if (LASTL) {
            #pragma unroll
            for (int mt = 0; mt < MT; mt++) { rowsq[mt][0] = 0.f; rowsq[mt][1] = 0.f; }
        }
        #pragma unroll
        for (int nt = 0; nt < NT; nt++) {
            int c0 = nbase + nt * 8 + 2 * r;
            float b0 = bias[c0], b1 = bias[c0 + 1];
            #pragma unroll
            for (int mt = 0; mt < MT; mt++) {
                int m0 = mt * 16 + q, m1 = m0 + 8;
                float2 f0 = __half22float2(*(__half2*)&hacc[mt][nt][0]);
                float2 f1 = __half22float2(*(__half2*)&hacc[mt][nt][1]);
                float v00 = fmaxf(f0.x + b0, 0.f);
                float v01 = fmaxf(f0.y + b1, 0.f);
                float v10 = fmaxf(f1.x + b0, 0.f);
                float v11 = fmaxf(f1.y + b1, 0.f);
                if (LASTL) {
                    float* C = (float*)Cout;
                    *(float2*)&C[m0 * CSTR + c0] = make_float2(v00, v01);
                    *(float2*)&C[m1 * CSTR + c0] = make_float2(v10, v11);
                    rowsq[mt][0] += v00 * v00 + v01 * v01;
                    rowsq[mt][1] += v10 * v10 + v11 * v11;
                } else {
                    __half* C = (__half*)Cout;
                    *(__half2*)&C[m0 * CSTR + c0] = __floats2half2_rn(v00, v01);
                    *(__half2*)&C[m1 * CSTR + c0] = __floats2half2_rn(v10, v11);
                }
            }
        }
        if (LASTL) {
            #pragma unroll
            for (int mt = 0; mt < MT; mt++) {
                float s0 = rowsq[mt][0], s1 = rowsq[mt][1];
                s0 += __shfl_xor_sync(0xffffffffu, s0, 1);
                s0 += __shfl_xor_sync(0xffffffffu, s0, 2);
                s1 += __shfl_xor_sync(0xffffffffu, s1, 1);
                s1 += __shfl_xor_sync(0xffffffffu, s1, 2);
                if (r == 0) {
                    atomicAdd(&sSq[mt * 16 + q], s0);
                    atomicAdd(&sSq[mt * 16 + q + 8], s1);
                }
            }
        }
    }
}

// ---------------- kernel 3 (ncu launch index 3): fused MLP ----------------
// smem bytes: bufB_h 64*520*2=66560 (overlay bufF f32 64*132*4=33792)
//             bufA_h 64*264*2=33792 (overlay sSum 2*13*128*4=13312 after L4)
//             bufI_h 64*24*2=3072,  extras 1024   -> 104448 total (2 CTAs/SM)
#define SMEM_BYTES (66560 + 33792 + 3072 + 1024)

__global__ __launch_bounds__(NTHR, 2)
void mlp_kernel(const float* __restrict__ pos, const float* __restrict__ x,
                const int* __restrict__ y,
                const float* __restrict__ be1, const float* __restrict__ be2,
                const float* __restrict__ b1,  const float* __restrict__ b2,
                float* __restrict__ out, int P, int Npts)
{
    extern __shared__ __align__(16) char smraw[];
    __half* bufB = (__half*)smraw;                      // [64][520]
    __half* bufA = (__half*)(smraw + 66560);            // [64][264]
    __half* bufI = (__half*)(smraw + 66560 + 33792);    // [64][24]
    float*  sInv = (float*)(smraw + 66560 + 33792 + 3072);   // 64
    float*  sLbl = sInv + 64;                           // 64
    int*    sLab = (int*)(sLbl + 64);                   // 64
    float*  sSq  = (float*)(sLab + 64);                 // 64
    float*  bufF = (float*)smraw;                       // overlay [64][132]
    float*  sSum = (float*)(smraw + 66560);             // overlay 2*13*128

    const int tid  = threadIdx.x;
    const int lane = tid & 31, warp = tid >> 5;
    const int base = blockIdx.x * BM;

    // ---- load inputs into bufI [64][24]: one thread per point, div once ----
    if (tid < BM) {
        int p = base + tid;
        float v[8];
        #pragma unroll
        for (int c = 0; c < 8; c++) v[c] = 0.f;
        int l = 0;
        if (p < P) {
            int b = p / Npts, n = p - b * Npts;
            const float* xb = x + (size_t)b * 4 * Npts + n;
            v[0] = xb[0];
            v[1] = xb[Npts];
            v[2] = xb[2 * Npts];
            v[3] = xb[3 * Npts];
            const float* pp = pos + (size_t)p * 3;
            v[4] = pp[0]; v[5] = pp[1]; v[6] = pp[2];
            l = y[p];
        }
        __half* dst = bufI + tid * 24;
        #pragma unroll
        for (int c = 0; c < 8; c += 2)
            *(__half2*)&dst[c] = __floats2half2_rn(v[c], v[c + 1]);
        *(__half2*)&dst[8]  = __floats2half2_rn(0.f, 0.f);
        *(__half2*)&dst[10] = __floats2half2_rn(0.f, 0.f);
        *(__half2*)&dst[12] = __floats2half2_rn(0.f, 0.f);
        *(__half2*)&dst[14] = __floats2half2_rn(0.f, 0.f);
        sLab[tid] = l;
        float cnt = (float)g_counts[l];
        sLbl[tid] = (cnt >= MINPTS) ? (float)l : -1.f;
        sSq[tid]  = 0.f;
    }
    __syncthreads();

    // ---- MLP chain (f16-acc single chain; ldmatrix A loads) ----
    mma_layer<16,  256, 24,  264, 4, 4, false>(g_wp + OFF1, be1, bufI, bufA, sSq, warp, lane);
    __syncthreads();
    mma_layer<256, 512, 264, 520, 4, 4, false>(g_wp + OFF2, be2, bufA, bufB, sSq, warp, lane);
    __syncthreads();
    mma_layer<512, 256, 520, 264, 4, 4, false>(g_wp + OFF3, b1,  bufB, bufA, sSq, warp, lane);
    __syncthreads();
    mma_layer<256, 128, 264, 132, 4, 2, true >(g_wp + OFF4, b2,  bufA, bufF, sSq, warp, lane);
    __syncthreads();

    // ---- zero sum overlay (bufA dead now) + row inverse norms from fused ssq ----
    for (int i = tid; i < 2 * NCLS * PD; i += NTHR) sSum[i] = 0.f;
    if (tid < BM)
        sInv[tid] = 1.f / fmaxf(sqrtf(sSq[tid]), 1e-12f);
    __syncthreads();

    // ---- per-class sums (2 race-free shared copies) ----
    {
        int n = tid & 127, half = tid >> 7;
        float* dst = sSum + half * NCLS * PD + n;
        for (int mm = 0; mm < 32; mm++) {
            int m = (half << 5) + mm;
            if (base + m < P)
                dst[sLab[m] * PD] += bufF[m * 132 + n] * sInv[m];
        }
    }
    __syncthreads();
    for (int i = tid; i < NCLS * PD; i += NTHR)
        atomicAdd(&g_sums[i], sSum[i] + sSum[NCLS * PD + i]);

    // ---- write current_prior rows [64][129] (incremental addressing) ----
    {
        size_t gbase = (size_t)base * 129;
        int c = tid & 127, mrow = tid >> 7;              // 2 rows x 128 cols per pass
        const float* src = bufF + mrow * 132 + c;
        float* dst = out + gbase + (size_t)mrow * 129 + c;
        for (int mm = mrow; mm < BM; mm += 2) {
            if (base + mm < P) *dst = (*src) * sInv[mm];
            src += 2 * 132;
            dst += 2 * 129;
        }
        for (int mm = tid; mm < BM; mm += NTHR)
            if (base + mm < P) out[gbase + (size_t)mm * 129 + 128] = sLbl[mm];
    }
}

// ---------------- kernel 4: EMA prior update (one warp per class) ----------------
__global__ void prior_kernel(const float* __restrict__ prior, float* __restrict__ out, int P) {
    int w = threadIdx.x >> 5;
    int lane = threadIdx.x & 31;
    if (w >= NCLS) return;
    float cnt = (float)g_counts[w];
    bool valid = (cnt >= MINPTS);
    float inv_cnt = 1.f / fmaxf(cnt, 1.f);
    float4 s4 = *(const float4*)&g_sums[w * PD + lane * 4];
    float4 p4 = *(const float4*)&prior[w * PD + lane * 4];
    float v[4];
    float pe[4] = {p4.x, p4.y, p4.z, p4.w};
    float mn[4] = {s4.x * inv_cnt, s4.y * inv_cnt, s4.z * inv_cnt, s4.w * inv_cnt};
    float ss = 0.f;
    #pragma unroll
    for (int i = 0; i < 4; i++) {
        float cur = valid ? mn[i] : pe[i];
        v[i] = 0.999f * pe[i] + 0.001f * cur;
        ss += v[i] * v[i];
    }
    #pragma unroll
    for (int o = 16; o > 0; o >>= 1) ss += __shfl_xor_sync(0xffffffffu, ss, o);
    float inv = 1.f / fmaxf(sqrtf(ss), 1e-12f);
    *(float4*)&out[(size_t)P * 129 + w * PD + lane * 4] =
        make_float4(v[0] * inv, v[1] * inv, v[2] * inv, v[3] * inv);
}

// ---------------- launch (mlp_kernel is launch index 3) ----------------
extern "C" void kernel_launch(void* const* d_in, const int* in_sizes, int n_in,
                              void* d_out, int out_size)
{
    const float* pos = (const float*)d_in[0];
    const float* x   = (const float*)d_in[1];
    const int*   y   = (const int*)  d_in[2];
    const float* We1 = (const float*)d_in[3];
    const float* be1 = (const float*)d_in[4];
    const float* We2 = (const float*)d_in[5];
    const float* be2 = (const float*)d_in[6];
    const float* W1  = (const float*)d_in[7];
    const float* b1  = (const float*)d_in[8];
    const float* W2  = (const float*)d_in[9];
    const float* b2  = (const float*)d_in[10];
    const float* pe  = (const float*)d_in[11];
    float* out = (float*)d_out;

    int P    = in_sizes[2];
    int B    = in_sizes[0] / 3 / 40000;
    int Npts = (B > 0) ? (in_sizes[0] / 3 / B) : 40000;

    cudaFuncSetAttribute(mlp_kernel, cudaFuncAttributeMaxDynamicSharedMemorySize, SMEM_BYTES);

    zero_kernel<<<1, 256>>>();                               // 0
    count_kernel<<<296, 256>>>(y, P);                        // 1
    pack_all_kernel<<<(WPTOT + 255) / 256, 256>>>(We1, We2, W1, W2); // 2
    mlp_kernel<<<(P + BM - 1) / BM, NTHR, SMEM_BYTES>>>(pos, x, y, be1, be2,
                                                        b1, b2, out, P, Npts); // 3
    prior_kernel<<<1, 416>>>(pe, out, P);                    // 4
}